// round 3
// baseline (speedup 1.0000x reference)
#include <cuda_runtime.h>
#include <math.h>

#define NNODES 100000
#define FIN    512
#define HID    256
#define NC     40
#define ZPAD   64            // padded row stride for z/h (256B-aligned rows)
#define KSTEPS 10
#define EMAX   3200000
#define ALPHA  0.1f

// ---------------- device scratch (no allocations allowed) ----------------
__device__ float g_hid[NNODES * HID];        // ~102 MB
__device__ float g_h  [NNODES * ZPAD];       // 25.6 MB (padded)
__device__ float g_zA [NNODES * ZPAD];
__device__ float g_zB [NNODES * ZPAD];
__device__ float g_dinv[NNODES];
__device__ int   g_deg [NNODES];
__device__ int   g_rowptr[NNODES + 1];
__device__ int   g_fill[NNODES];
__device__ int   g_colidx[EMAX];
__device__ float g_ew   [EMAX];

// ---------------- packed f32x2 helpers (sm_103a FFMA2 via PTX) ----------------
__device__ __forceinline__ void fma2(unsigned long long &d, unsigned long long a,
                                     unsigned long long b) {
    asm("fma.rn.f32x2 %0, %1, %2, %3;" : "=l"(d) : "l"(a), "l"(b), "l"(d));
}
__device__ __forceinline__ unsigned long long pack2(float v) {
    unsigned long long r;
    unsigned int u = __float_as_uint(v);
    asm("mov.b64 %0, {%1, %2};" : "=l"(r) : "r"(u), "r"(u));
    return r;
}
__device__ __forceinline__ float2 unpack2(unsigned long long p) {
    unsigned int lo, hi;
    asm("mov.b64 {%0, %1}, %2;" : "=r"(lo), "=r"(hi) : "l"(p));
    return make_float2(__uint_as_float(lo), __uint_as_float(hi));
}

// ---------------- graph preprocessing ----------------
__global__ void zero_deg_kernel() {
    int i = blockIdx.x * blockDim.x + threadIdx.x;
    if (i < NNODES) g_deg[i] = 0;
}

__global__ void count_deg_kernel(const int* __restrict__ ei, int E) {
    int e = blockIdx.x * blockDim.x + threadIdx.x;
    if (e < E) atomicAdd(&g_deg[ei[e]], 1);
}

// single-block exclusive scan over g_deg -> g_rowptr, also dinv + fill init
__global__ void scan_kernel(int E) {
    const int T = 1024;
    const int CH = (NNODES + T - 1) / T;
    int t = threadIdx.x;
    int beg = t * CH;
    int end = beg + CH; if (end > NNODES) end = NNODES;
    if (beg > NNODES) beg = NNODES;

    int sum = 0;
    for (int i = beg; i < end; i++) sum += g_deg[i];

    __shared__ int sh[1024];
    sh[t] = sum;
    __syncthreads();
    for (int off = 1; off < T; off <<= 1) {
        int v = (t >= off) ? sh[t - off] : 0;
        __syncthreads();
        sh[t] += v;
        __syncthreads();
    }
    int offset = sh[t] - sum;

    int running = offset;
    for (int i = beg; i < end; i++) {
        g_rowptr[i] = running;
        g_fill[i]   = running;
        g_dinv[i]   = rsqrtf((float)(g_deg[i] + 1));   // +1 self-loop
        running += g_deg[i];
    }
    if (t == T - 1) g_rowptr[NNODES] = sh[T - 1];
}

__global__ void scatter_kernel(const int* __restrict__ ei, int E) {
    int e = blockIdx.x * blockDim.x + threadIdx.x;
    if (e >= E) return;
    int r = ei[e];          // destination
    int c = ei[E + e];      // source
    int pos = atomicAdd(&g_fill[r], 1);
    g_colidx[pos] = c;
    g_ew[pos] = g_dinv[r] * g_dinv[c];
}

// ---------------- GEMM1: h1 = relu(x @ W1 + b1)  [100000,512]x[512,256] ----------------
// BM=128 BN=128 BK=16, 256 threads, thread tile 8x8 via f32x2, double-buffered smem
__global__ __launch_bounds__(256, 2) void gemm1_kernel(
    const float* __restrict__ X, const float* __restrict__ W1, const float* __restrict__ b1)
{
    __shared__ __align__(16) float As[2][16][132];   // [k][m], pad 132 (16B-divisible)
    __shared__ __align__(16) float Bs[2][16][132];   // [k][n]

    const int tid = threadIdx.x;
    const int m0 = blockIdx.x * 128;
    const int n0 = blockIdx.y * 128;

    const int tx = tid & 15;       // n: 16 groups x 8 cols
    const int ty = tid >> 4;       // m: 16 groups x 8 rows

    unsigned long long acc[8][4];
    #pragma unroll
    for (int i = 0; i < 8; i++)
        #pragma unroll
        for (int p = 0; p < 4; p++) acc[i][p] = 0ULL;

    // per-thread LDG staging regs
    float4 ar[2], br[2];
    const int qa0 = tid, qa1 = tid + 256;

    // prologue: tile 0
    {
        const int k0 = 0;
        #pragma unroll
        for (int l = 0; l < 2; l++) {
            int q = tid + l * 256;
            int m = q >> 2, kq = q & 3;
            int row = m0 + m; if (row > NNODES - 1) row = NNODES - 1;
            (l == 0 ? ar[0] : ar[1]) = *(const float4*)&X[(size_t)row * FIN + k0 + kq * 4];
        }
        #pragma unroll
        for (int l = 0; l < 2; l++) {
            int q = tid + l * 256;
            int kr = q >> 5, nq = q & 31;
            (l == 0 ? br[0] : br[1]) = *(const float4*)&W1[(size_t)(k0 + kr) * HID + n0 + nq * 4];
        }
        #pragma unroll
        for (int l = 0; l < 2; l++) {
            int q = tid + l * 256;
            int m = q >> 2, kq = q & 3;
            float4 v = ar[l];
            As[0][kq * 4 + 0][m] = v.x;
            As[0][kq * 4 + 1][m] = v.y;
            As[0][kq * 4 + 2][m] = v.z;
            As[0][kq * 4 + 3][m] = v.w;
        }
        #pragma unroll
        for (int l = 0; l < 2; l++) {
            int q = tid + l * 256;
            int kr = q >> 5, nq = q & 31;
            *(float4*)&Bs[0][kr][nq * 4] = br[l];
        }
    }
    __syncthreads();

    const int TILES = FIN / 16;   // 32
    for (int t = 0; t < TILES; t++) {
        int buf = t & 1;

        if (t + 1 < TILES) {
            int k0 = (t + 1) * 16;
            #pragma unroll
            for (int l = 0; l < 2; l++) {
                int q = tid + l * 256;
                int m = q >> 2, kq = q & 3;
                int row = m0 + m; if (row > NNODES - 1) row = NNODES - 1;
                ar[l] = *(const float4*)&X[(size_t)row * FIN + k0 + kq * 4];
            }
            #pragma unroll
            for (int l = 0; l < 2; l++) {
                int q = tid + l * 256;
                int kr = q >> 5, nq = q & 31;
                br[l] = *(const float4*)&W1[(size_t)(k0 + kr) * HID + n0 + nq * 4];
            }
        }

        #pragma unroll
        for (int k = 0; k < 16; k++) {
            float4 a0 = *(float4*)&As[buf][k][ty * 8];
            float4 a1 = *(float4*)&As[buf][k][ty * 8 + 4];
            unsigned long long bb[4];
            {
                ulonglong2 b0 = *(ulonglong2*)&Bs[buf][k][tx * 8];
                ulonglong2 b1 = *(ulonglong2*)&Bs[buf][k][tx * 8 + 4];
                bb[0] = b0.x; bb[1] = b0.y; bb[2] = b1.x; bb[3] = b1.y;
            }
            float av[8] = {a0.x, a0.y, a0.z, a0.w, a1.x, a1.y, a1.z, a1.w};
            #pragma unroll
            for (int i = 0; i < 8; i++) {
                unsigned long long aa = pack2(av[i]);
                #pragma unroll
                for (int p = 0; p < 4; p++) fma2(acc[i][p], aa, bb[p]);
            }
        }

        if (t + 1 < TILES) {
            int nb = buf ^ 1;
            #pragma unroll
            for (int l = 0; l < 2; l++) {
                int q = tid + l * 256;
                int m = q >> 2, kq = q & 3;
                float4 v = ar[l];
                As[nb][kq * 4 + 0][m] = v.x;
                As[nb][kq * 4 + 1][m] = v.y;
                As[nb][kq * 4 + 2][m] = v.z;
                As[nb][kq * 4 + 3][m] = v.w;
            }
            #pragma unroll
            for (int l = 0; l < 2; l++) {
                int q = tid + l * 256;
                int kr = q >> 5, nq = q & 31;
                *(float4*)&Bs[nb][kr][nq * 4] = br[l];
            }
        }
        __syncthreads();
    }

    float bias[8];
    #pragma unroll
    for (int j = 0; j < 8; j++) bias[j] = b1[n0 + tx * 8 + j];

    #pragma unroll
    for (int i = 0; i < 8; i++) {
        int m = m0 + ty * 8 + i;
        if (m < NNODES) {
            float o[8];
            #pragma unroll
            for (int p = 0; p < 4; p++) {
                float2 v = unpack2(acc[i][p]);
                o[p * 2]     = fmaxf(v.x + bias[p * 2], 0.0f);
                o[p * 2 + 1] = fmaxf(v.y + bias[p * 2 + 1], 0.0f);
            }
            float* dst = &g_hid[(size_t)m * HID + n0 + tx * 8];
            *(float4*)dst       = make_float4(o[0], o[1], o[2], o[3]);
            *(float4*)(dst + 4) = make_float4(o[4], o[5], o[6], o[7]);
        }
    }
}

// ---------------- GEMM2: h = hid @ W2 + b2  [100000,256]x[256,40] ----------------
// BM=128 BK=32, 256 threads, thread tile 2 rows x 10 cols (5 f32x2 pairs)
__global__ __launch_bounds__(256) void gemm2_kernel(
    const float* __restrict__ W2, const float* __restrict__ b2)
{
    __shared__ __align__(8) float Hs[32][133];   // [k][m], pad 133 -> conflict-free STS
    __shared__ __align__(8) float Ws[32][40];    // [k][n]

    const int tid = threadIdx.x;
    const int m0 = blockIdx.x * 128;
    const int tx = tid & 3;        // 4 groups x 10 cols = 40
    const int ty = tid >> 2;       // 64 groups x 2 rows = 128

    unsigned long long acc0[5], acc1[5];
    #pragma unroll
    for (int j = 0; j < 5; j++) { acc0[j] = 0ULL; acc1[j] = 0ULL; }

    for (int k0 = 0; k0 < HID; k0 += 32) {
        // Hs: 128 rows x 32 k, coalesced over k
        {
            int kk = tid & 31;
            int mb = tid >> 5;     // 0..7
            #pragma unroll
            for (int mi = 0; mi < 16; mi++) {
                int m = mi * 8 + mb;
                int row = m0 + m; if (row > NNODES - 1) row = NNODES - 1;
                Hs[kk][m] = g_hid[(size_t)row * HID + k0 + kk];
            }
        }
        // Ws: 32 x 40 = 1280 floats, 5 per thread
        #pragma unroll
        for (int l = 0; l < 5; l++) {
            int idx = tid + l * 256;
            int kr = idx / 40;
            int n = idx - kr * 40;
            Ws[kr][n] = W2[(size_t)(k0 + kr) * NC + n];
        }
        __syncthreads();

        #pragma unroll
        for (int k = 0; k < 32; k++) {
            unsigned long long aa0 = pack2(Hs[k][ty * 2]);
            unsigned long long aa1 = pack2(Hs[k][ty * 2 + 1]);
            #pragma unroll
            for (int j = 0; j < 5; j++) {
                unsigned long long bb = *(unsigned long long*)&Ws[k][tx * 10 + 2 * j];
                fma2(acc0[j], aa0, bb);
                fma2(acc1[j], aa1, bb);
            }
        }
        __syncthreads();
    }

    #pragma unroll
    for (int r = 0; r < 2; r++) {
        int m = m0 + ty * 2 + r;
        if (m < NNODES) {
            float* dst = &g_h[(size_t)m * ZPAD];
            #pragma unroll
            for (int j = 0; j < 5; j++) {
                int n = tx * 10 + 2 * j;
                float2 v = unpack2(r == 0 ? acc0[j] : acc1[j]);
                dst[n]     = v.x + b2[n];
                dst[n + 1] = v.y + b2[n + 1];
            }
        }
    }
}

// ---------------- APPNP propagation step: zout = 0.9*A_norm*zin + 0.1*h ----------------
// warp per row, lane c handles channels c and (c+32 if c<8); rows padded to 256B
__global__ __launch_bounds__(256) void spmm_kernel(int srcSel, int dstSel) {
    const float* zin  = (srcSel == 0) ? g_h : (srcSel == 1 ? g_zA : g_zB);
    float*       zout = (dstSel == 1) ? g_zA : g_zB;

    int w = (blockIdx.x * blockDim.x + threadIdx.x) >> 5;
    int lane = threadIdx.x & 31;
    if (w >= NNODES) return;
    int r = w;
    int s = g_rowptr[r];
    int e = g_rowptr[r + 1];

    float acc0 = 0.0f, acc1 = 0.0f;
    #pragma unroll 4
    for (int j = s; j < e; j++) {
        float wt = __ldg(&g_ew[j]);
        int ci = __ldg(&g_colidx[j]);
        const float* zb = zin + (size_t)ci * ZPAD;
        acc0 += wt * zb[lane];
        if (lane < 8) acc1 += wt * zb[32 + lane];
    }
    // self loop
    float dv = g_dinv[r];
    float ws = dv * dv;
    const float* zr = zin + (size_t)r * ZPAD;
    acc0 += ws * zr[lane];
    if (lane < 8) acc1 += ws * zr[32 + lane];

    const float* hr = g_h + (size_t)r * ZPAD;
    float* zo = zout + (size_t)r * ZPAD;
    zo[lane] = (1.0f - ALPHA) * acc0 + ALPHA * hr[lane];
    if (lane < 8) zo[32 + lane] = (1.0f - ALPHA) * acc1 + ALPHA * hr[32 + lane];
}

// ---------------- log_softmax over 40 classes, warp per row ----------------
__global__ __launch_bounds__(256) void logsoftmax_kernel(float* __restrict__ out) {
    int w = (blockIdx.x * blockDim.x + threadIdx.x) >> 5;
    int lane = threadIdx.x & 31;
    if (w >= NNODES) return;

    const float* zr = g_zB + (size_t)w * ZPAD;
    float v0 = zr[lane];
    float v1 = (lane < 8) ? zr[32 + lane] : -3.4e38f;

    float m = fmaxf(v0, v1);
    #pragma unroll
    for (int off = 16; off > 0; off >>= 1)
        m = fmaxf(m, __shfl_xor_sync(0xffffffff, m, off));

    float s = __expf(v0 - m) + ((lane < 8) ? __expf(v1 - m) : 0.0f);
    #pragma unroll
    for (int off = 16; off > 0; off >>= 1)
        s += __shfl_xor_sync(0xffffffff, s, off);

    float lse = m + logf(s);
    float* o = out + (size_t)w * NC;
    o[lane] = v0 - lse;
    if (lane < 8) o[32 + lane] = v1 - lse;
}

// ---------------- launch ----------------
extern "C" void kernel_launch(void* const* d_in, const int* in_sizes, int n_in,
                              void* d_out, int out_size) {
    const float* x  = (const float*)d_in[0];
    const float* W1 = (const float*)d_in[1];
    const float* b1 = (const float*)d_in[2];
    const float* W2 = (const float*)d_in[3];
    const float* b2 = (const float*)d_in[4];
    const int*   ei = (const int*)d_in[5];
    float* out = (float*)d_out;
    int E = in_sizes[5] / 2;

    // graph preprocessing -> CSR + normalized weights
    zero_deg_kernel<<<(NNODES + 255) / 256, 256>>>();
    count_deg_kernel<<<(E + 255) / 256, 256>>>(ei, E);
    scan_kernel<<<1, 1024>>>(E);
    scatter_kernel<<<(E + 255) / 256, 256>>>(ei, E);

    // MLP encoder
    dim3 g1((NNODES + 127) / 128, HID / 128);
    gemm1_kernel<<<g1, 256>>>(x, W1, b1);
    gemm2_kernel<<<(NNODES + 127) / 128, 256>>>(W2, b2);

    // K=10 APPNP steps; src: 0=h 1=zA 2=zB, dst: 1=zA 2=zB
    int spmmGrid = (NNODES * 32 + 255) / 256;
    for (int i = 1; i <= KSTEPS; i++) {
        int src = (i == 1) ? 0 : ((i & 1) ? 2 : 1);
        int dst = (i & 1) ? 1 : 2;
        spmm_kernel<<<spmmGrid, 256>>>(src, dst);
    }

    // final z is in g_zB (K even)
    logsoftmax_kernel<<<spmmGrid, 256>>>(out);
}